// round 3
// baseline (speedup 1.0000x reference)
#include <cuda_runtime.h>
#include <cuda_bf16.h>
#include <cstdint>

// ============================================================
// Problem constants
// ============================================================
#define B_SZ  8
#define L_SZ  4096
#define CIN   1024
#define COUT  1024
#define WDIM  512

#define M_TILE   128
#define N_TILE   256
#define K_CHUNK  64                 // bf16 elems per chunk = 128 bytes (one SW128 row)
#define NCHUNK   (CIN / K_CHUNK)    // 16
#define NSTAGE   3

// SMEM layout (dynamic)
#define SM_BIAS   0                  // 256 floats
#define SM_LS     1024               // 256 floats
#define SM_STAGE  2048
#define A_BYTES   (M_TILE * 128)                 // 16384
#define STAGE_BYTES (A_BYTES + N_TILE * 128)     // 49152
#define SMEM_TOTAL (SM_STAGE + NSTAGE * STAGE_BYTES)  // 149504

// ============================================================
// Device scratch (allocation-free rule: __device__ globals)
// ============================================================
__device__ __align__(256) __nv_bfloat16 g_xbf[B_SZ * L_SZ * CIN];     // 64 MB
__device__ __align__(256) __nv_bfloat16 g_wmod[B_SZ * COUT * CIN];    // 16 MB
__device__ float g_styles[B_SZ * CIN];

// ============================================================
// Helpers
// ============================================================
#define DI __device__ __forceinline__

DI uint32_t smem_u32(const void* p) {
    uint32_t a;
    asm("{ .reg .u64 t; cvta.to.shared.u64 t, %1; cvt.u32.u64 %0, t; }" : "=r"(a) : "l"(p));
    return a;
}

#define SWZ(o) ((o) ^ (((o) >> 3) & 0x70))

DI void cp16(uint32_t dst, const void* src) {
    asm volatile("cp.async.cg.shared.global [%0], [%1], 16;\n" :: "r"(dst), "l"(src) : "memory");
}
template <int N> DI void cp_wait() {
    asm volatile("cp.async.wait_group %0;" :: "n"(N) : "memory");
}

DI void ldsm_x4(uint32_t* r, uint32_t addr) {
    asm volatile("ldmatrix.sync.aligned.m8n8.x4.shared.b16 {%0,%1,%2,%3}, [%4];"
                 : "=r"(r[0]), "=r"(r[1]), "=r"(r[2]), "=r"(r[3]) : "r"(addr));
}

DI void mma16816(float* c, const uint32_t* a, const uint32_t* b) {
    asm volatile(
        "mma.sync.aligned.m16n8k16.row.col.f32.bf16.bf16.f32 "
        "{%0,%1,%2,%3}, {%4,%5,%6,%7}, {%8,%9}, {%0,%1,%2,%3};"
        : "+f"(c[0]), "+f"(c[1]), "+f"(c[2]), "+f"(c[3])
        : "r"(a[0]), "r"(a[1]), "r"(a[2]), "r"(a[3]), "r"(b[0]), "r"(b[1]));
}

// ============================================================
// Prep kernel 1: styles[b][i] = (w[b] . aff_w[i]) / sqrt(512) + aff_b[i]
// ============================================================
__global__ void k_styles(const float* __restrict__ w, const float* __restrict__ aff_w,
                         const float* __restrict__ aff_b) {
    __shared__ float ws[WDIM];
    const int b = blockIdx.x, t = threadIdx.x;
    for (int j = t; j < WDIM; j += 256) ws[j] = w[b * WDIM + j];
    __syncthreads();
    const float gain = 0.04419417382415922f;  // 1/sqrt(512)
    for (int i = t; i < CIN; i += 256) {
        const float4* ar = reinterpret_cast<const float4*>(aff_w + (size_t)i * WDIM);
        float s = 0.f;
        #pragma unroll 4
        for (int j = 0; j < WDIM / 4; j++) {
            float4 v = ar[j];
            s += v.x * ws[4*j] + v.y * ws[4*j+1] + v.z * ws[4*j+2] + v.w * ws[4*j+3];
        }
        g_styles[b * CIN + i] = s * gain + aff_b[i];
    }
}

// ============================================================
// Prep kernel 2: dcoef = rsqrt(sum_i (weight[o,i]*styles[b,i])^2 + 1e-8)
//                g_wmod[b][o][i] = bf16(weight*styles*dcoef)
// ============================================================
__global__ void k_wmod(const float* __restrict__ weight) {
    const int o = blockIdx.x, b = blockIdx.y, t = threadIdx.x;
    const float* wr = weight + (size_t)o * CIN;
    const float* sr = g_styles + b * CIN;
    float pv[8];
    float acc = 0.f;
    #pragma unroll
    for (int u = 0; u < 8; u++) {
        int i = t + u * 128;
        pv[u] = wr[i] * sr[i];
        acc += pv[u] * pv[u];
    }
    #pragma unroll
    for (int off = 16; off > 0; off >>= 1) acc += __shfl_xor_sync(0xffffffffu, acc, off);
    __shared__ float red[4];
    if ((t & 31) == 0) red[t >> 5] = acc;
    __syncthreads();
    float dco = rsqrtf(red[0] + red[1] + red[2] + red[3] + 1e-8f);
    __nv_bfloat16* dst = g_wmod + ((size_t)b * COUT + o) * CIN;
    #pragma unroll
    for (int u = 0; u < 8; u++) dst[t + u * 128] = __float2bfloat16(pv[u] * dco);
}

// ============================================================
// Prep kernel 3: x fp32 -> bf16
// ============================================================
__global__ void k_convert(const float* __restrict__ x) {
    size_t i = (size_t)blockIdx.x * 256 + threadIdx.x;  // one float4 each, exact cover
    const float4 v = reinterpret_cast<const float4*>(x)[i];
    __nv_bfloat162* o = reinterpret_cast<__nv_bfloat162*>(g_xbf) + 2 * i;
    o[0] = __float22bfloat162_rn(make_float2(v.x, v.y));
    o[1] = __float22bfloat162_rn(make_float2(v.z, v.w));
}

// ============================================================
// Main GEMM (HMMA mma.sync bf16) + fused epilogue
//   D[m][n] = sum_k xbf[b][m0+m][k] * wmod[b][n0+n][k]
//   out = clamp(lrelu(D + bias)*sqrt2, +-256)*layerscale + x
// ============================================================
DI float epi(float d, float bi, float l, float xres) {
    float v = d + bi;
    v = (v > 0.f) ? v : 0.2f * v;
    v *= 1.41421356237f;
    v = fminf(fmaxf(v, -256.f), 256.f);
    return fmaf(v, l, xres);
}

__global__ __launch_bounds__(256, 1)
void gemm_kernel(const float* __restrict__ x, const float* __restrict__ bias,
                 const float* __restrict__ ls, float* __restrict__ out) {
    extern __shared__ __align__(1024) char smem[];
    const uint32_t sb = smem_u32(smem);
    const int tid = threadIdx.x, wid = tid >> 5, lane = tid & 31;
    const int nb = blockIdx.x, mb = blockIdx.y, b = blockIdx.z;
    const int m0 = mb * M_TILE, n0 = nb * N_TILE;

    // warp layout: 2 (M) x 4 (N), warp tile 64x64
    const int wm = wid & 1, wn = wid >> 1;
    const int warp_m = wm * 64, warp_n = wn * 64;

    float* bias_s = (float*)(smem + SM_BIAS);
    float* ls_s   = (float*)(smem + SM_LS);
    bias_s[tid] = bias[n0 + tid];
    ls_s[tid]   = ls[n0 + tid];

    const __nv_bfloat16* xb = g_xbf + ((size_t)b * L_SZ + m0) * CIN;
    const __nv_bfloat16* wb = g_wmod + ((size_t)b * COUT + n0) * CIN;

    auto load_chunk = [&](int k, int s) {
        const uint32_t sA = sb + SM_STAGE + s * STAGE_BYTES;
        const uint32_t sB = sA + A_BYTES;
        #pragma unroll
        for (int i = 0; i < 4; i++) {  // A: 128 rows x 8 segs
            int seg = tid + i * 256; int r = seg >> 3, c = seg & 7;
            cp16(sA + SWZ(r * 128 + c * 16), xb + (size_t)r * CIN + k * K_CHUNK + c * 8);
        }
        #pragma unroll
        for (int i = 0; i < 8; i++) {  // B: 256 rows x 8 segs
            int seg = tid + i * 256; int r = seg >> 3, c = seg & 7;
            cp16(sB + SWZ(r * 128 + c * 16), wb + (size_t)r * CIN + k * K_CHUNK + c * 8);
        }
        asm volatile("cp.async.commit_group;" ::: "memory");
    };

    load_chunk(0, 0);
    load_chunk(1, 1);
    load_chunk(2, 2);

    // per-lane ldmatrix address pieces (offsets within a stage)
    // A frag (m16k16): row = warp_m + mf*16 + ((lane>>3)&1)*8 + (lane&7); k8-half = lane>>4
    const int a_row = warp_m + ((lane >> 3) & 1) * 8 + (lane & 7);
    const uint32_t a_xor = (uint32_t)((a_row & 7) << 4);
    const uint32_t a_rt0 = (uint32_t)(a_row * 128);
    const uint32_t a_kh  = (uint32_t)((lane >> 4) * 16);   // bytes
    // B frag pair (n16k16): row = warp_n + nf2*16 + (lane>>4)*8 + (lane&7); k8-half = (lane>>3)&1
    const int b_row = warp_n + (lane >> 4) * 8 + (lane & 7);
    const uint32_t b_xor = (uint32_t)((b_row & 7) << 4);
    const uint32_t b_rt0 = (uint32_t)(b_row * 128);
    const uint32_t b_kh  = (uint32_t)(((lane >> 3) & 1) * 16);

    float acc[4][8][4];
    #pragma unroll
    for (int i = 0; i < 4; i++)
        #pragma unroll
        for (int j = 0; j < 8; j++)
            #pragma unroll
            for (int q = 0; q < 4; q++) acc[i][j][q] = 0.f;

    #pragma unroll 1
    for (int k = 0; k < NCHUNK; k++) {
        const int s = k % NSTAGE;
        if (k <= NCHUNK - 3)      cp_wait<2>();
        else if (k == NCHUNK - 2) cp_wait<1>();
        else                      cp_wait<0>();
        __syncthreads();

        const uint32_t sA = sb + SM_STAGE + s * STAGE_BYTES;
        const uint32_t sB = sA + A_BYTES;

        #pragma unroll
        for (int kk = 0; kk < 4; kk++) {
            const uint32_t acol = (uint32_t)(kk * 32) + a_kh;
            const uint32_t bcol = (uint32_t)(kk * 32) + b_kh;
            uint32_t af[4][4];
            #pragma unroll
            for (int mf = 0; mf < 4; mf++)
                ldsm_x4(af[mf], sA + a_rt0 + (uint32_t)(mf * 16 * 128) + (acol ^ a_xor));
            uint32_t bf[4][4];
            #pragma unroll
            for (int nf = 0; nf < 4; nf++)
                ldsm_x4(bf[nf], sB + b_rt0 + (uint32_t)(nf * 16 * 128) + (bcol ^ b_xor));
            #pragma unroll
            for (int mf = 0; mf < 4; mf++)
                #pragma unroll
                for (int nn = 0; nn < 8; nn++)
                    mma16816(acc[mf][nn], af[mf], &bf[nn >> 1][(nn & 1) * 2]);
        }

        __syncthreads();
        if (k + NSTAGE < NCHUNK) load_chunk(k + NSTAGE, s);
    }

    // ---------------- Epilogue ----------------
    const int qr = lane >> 2;          // 0..7
    const int qc = (lane & 3) * 2;     // 0,2,4,6
    #pragma unroll
    for (int mf = 0; mf < 4; mf++) {
        #pragma unroll
        for (int half = 0; half < 2; half++) {
            const int row = warp_m + mf * 16 + qr + half * 8;
            const size_t rowoff = ((size_t)b * L_SZ + m0 + row) * COUT + n0;
            const float* xr = x + rowoff;
            float* outr = out + rowoff;
            #pragma unroll
            for (int nn = 0; nn < 8; nn++) {
                const int c = warp_n + nn * 8 + qc;
                const float d0 = acc[mf][nn][half * 2 + 0];
                const float d1 = acc[mf][nn][half * 2 + 1];
                const float2 xv = *reinterpret_cast<const float2*>(xr + c);
                float2 ov;
                ov.x = epi(d0, bias_s[c],     ls_s[c],     xv.x);
                ov.y = epi(d1, bias_s[c + 1], ls_s[c + 1], xv.y);
                *reinterpret_cast<float2*>(outr + c) = ov;
            }
        }
    }
}

// ============================================================
// Launch
// ============================================================
extern "C" void kernel_launch(void* const* d_in, const int* in_sizes, int n_in,
                              void* d_out, int out_size) {
    (void)in_sizes; (void)n_in; (void)out_size;
    const float* x      = (const float*)d_in[0];
    const float* w      = (const float*)d_in[1];
    const float* weight = (const float*)d_in[2];
    const float* bias   = (const float*)d_in[3];
    const float* aff_w  = (const float*)d_in[4];
    const float* aff_b  = (const float*)d_in[5];
    const float* lsc    = (const float*)d_in[6];
    float* out = (float*)d_out;

    cudaFuncSetAttribute(gemm_kernel, cudaFuncAttributeMaxDynamicSharedMemorySize, SMEM_TOTAL);

    k_styles<<<B_SZ, 256>>>(w, aff_w, aff_b);
    k_wmod<<<dim3(COUT, B_SZ), 128>>>(weight);
    k_convert<<<(B_SZ * L_SZ * CIN / 4) / 256, 256>>>(x);
    gemm_kernel<<<dim3(COUT / N_TILE, L_SZ / M_TILE, B_SZ), 256, SMEM_TOTAL>>>(x, bias, lsc, out);
}

// round 4
// speedup vs baseline: 1.3633x; 1.3633x over previous
#include <cuda_runtime.h>
#include <cuda_bf16.h>
#include <cstdint>

// ============================================================
// Problem constants
// ============================================================
#define B_SZ  8
#define L_SZ  4096
#define CIN   1024
#define COUT  1024
#define WDIM  512

#define M_TILE   128
#define N_TILE   128
#define K_CHUNK  64                 // bf16 elems per chunk = 128 bytes (one SW128 row)
#define NCHUNK   (CIN / K_CHUNK)    // 16
#define NSTAGE   3
#define NTHREADS 128

// SMEM layout (dynamic)
#define SM_BIAS   0                  // 128 floats
#define SM_LS     512                // 128 floats
#define SM_STAGE  1024
#define A_BYTES   (M_TILE * 128)                 // 16384
#define STAGE_BYTES (A_BYTES + N_TILE * 128)     // 32768
#define SMEM_TOTAL (SM_STAGE + NSTAGE * STAGE_BYTES)  // 99328 -> 2 CTAs/SM

// ============================================================
// Device scratch (allocation-free rule: __device__ globals)
// ============================================================
__device__ __align__(256) __nv_bfloat16 g_xbf[B_SZ * L_SZ * CIN];     // 64 MB
__device__ __align__(256) __nv_bfloat16 g_wmod[B_SZ * COUT * CIN];    // 16 MB
__device__ float g_styles[B_SZ * CIN];

// ============================================================
// Helpers
// ============================================================
#define DI __device__ __forceinline__

DI uint32_t smem_u32(const void* p) {
    uint32_t a;
    asm("{ .reg .u64 t; cvta.to.shared.u64 t, %1; cvt.u32.u64 %0, t; }" : "=r"(a) : "l"(p));
    return a;
}

#define SWZ(o) ((o) ^ (((o) >> 3) & 0x70))

DI void cp16(uint32_t dst, const void* src) {
    asm volatile("cp.async.cg.shared.global [%0], [%1], 16;\n" :: "r"(dst), "l"(src) : "memory");
}
template <int N> DI void cp_wait() {
    asm volatile("cp.async.wait_group %0;" :: "n"(N) : "memory");
}

DI void ldsm_x4(uint32_t* r, uint32_t addr) {
    asm volatile("ldmatrix.sync.aligned.m8n8.x4.shared.b16 {%0,%1,%2,%3}, [%4];"
                 : "=r"(r[0]), "=r"(r[1]), "=r"(r[2]), "=r"(r[3]) : "r"(addr));
}

DI void mma16816(float* c, const uint32_t* a, const uint32_t* b) {
    asm volatile(
        "mma.sync.aligned.m16n8k16.row.col.f32.bf16.bf16.f32 "
        "{%0,%1,%2,%3}, {%4,%5,%6,%7}, {%8,%9}, {%0,%1,%2,%3};"
        : "+f"(c[0]), "+f"(c[1]), "+f"(c[2]), "+f"(c[3])
        : "r"(a[0]), "r"(a[1]), "r"(a[2]), "r"(a[3]), "r"(b[0]), "r"(b[1]));
}

// ============================================================
// Prep kernel 1: styles[b][i] = (w[b] . aff_w[i]) / sqrt(512) + aff_b[i]
//   grid (B, 8): each block covers 128 channels, one thread per channel.
// ============================================================
__global__ void k_styles(const float* __restrict__ w, const float* __restrict__ aff_w,
                         const float* __restrict__ aff_b) {
    __shared__ float ws[WDIM];
    const int b = blockIdx.x, cblk = blockIdx.y, t = threadIdx.x;
    for (int j = t; j < WDIM; j += 128) ws[j] = w[b * WDIM + j];
    __syncthreads();
    const float gain = 0.04419417382415922f;  // 1/sqrt(512)
    const int i = cblk * 128 + t;
    const float4* ar = reinterpret_cast<const float4*>(aff_w + (size_t)i * WDIM);
    float s0 = 0.f, s1 = 0.f, s2 = 0.f, s3 = 0.f;
    #pragma unroll 8
    for (int j = 0; j < WDIM / 4; j++) {
        float4 v = ar[j];
        s0 += v.x * ws[4*j];   s1 += v.y * ws[4*j+1];
        s2 += v.z * ws[4*j+2]; s3 += v.w * ws[4*j+3];
    }
    g_styles[b * CIN + i] = (s0 + s1 + s2 + s3) * gain + aff_b[i];
}

// ============================================================
// Prep kernel 2: dcoef = rsqrt(sum_i (weight[o,i]*styles[b,i])^2 + 1e-8)
//                g_wmod[b][o][i] = bf16(weight*styles*dcoef)
// ============================================================
__global__ void k_wmod(const float* __restrict__ weight) {
    const int o = blockIdx.x, b = blockIdx.y, t = threadIdx.x;
    const float* wr = weight + (size_t)o * CIN;
    const float* sr = g_styles + b * CIN;
    float pv[8];
    float acc = 0.f;
    #pragma unroll
    for (int u = 0; u < 8; u++) {
        int i = t + u * 128;
        pv[u] = wr[i] * sr[i];
        acc += pv[u] * pv[u];
    }
    #pragma unroll
    for (int off = 16; off > 0; off >>= 1) acc += __shfl_xor_sync(0xffffffffu, acc, off);
    __shared__ float red[4];
    if ((t & 31) == 0) red[t >> 5] = acc;
    __syncthreads();
    float dco = rsqrtf(red[0] + red[1] + red[2] + red[3] + 1e-8f);
    __nv_bfloat16* dst = g_wmod + ((size_t)b * COUT + o) * CIN;
    #pragma unroll
    for (int u = 0; u < 8; u++) dst[t + u * 128] = __float2bfloat16(pv[u] * dco);
}

// ============================================================
// Prep kernel 3: x fp32 -> bf16
// ============================================================
__global__ void k_convert(const float* __restrict__ x) {
    size_t i = (size_t)blockIdx.x * 256 + threadIdx.x;  // one float4 each, exact cover
    const float4 v = reinterpret_cast<const float4*>(x)[i];
    __nv_bfloat162* o = reinterpret_cast<__nv_bfloat162*>(g_xbf) + 2 * i;
    o[0] = __float22bfloat162_rn(make_float2(v.x, v.y));
    o[1] = __float22bfloat162_rn(make_float2(v.z, v.w));
}

// ============================================================
// Main GEMM (HMMA mma.sync bf16) + fused epilogue
//   128x128 CTA tile, 128 threads (4 warps, 2x2, warp tile 64x64),
//   3-stage cp.async pipeline, 2 CTAs/SM.
// ============================================================
DI float epi(float d, float bi, float l, float xres) {
    float v = d + bi;
    v = (v > 0.f) ? v : 0.2f * v;
    v *= 1.41421356237f;
    v = fminf(fmaxf(v, -256.f), 256.f);
    return fmaf(v, l, xres);
}

__global__ __launch_bounds__(NTHREADS, 2)
void gemm_kernel(const float* __restrict__ x, const float* __restrict__ bias,
                 const float* __restrict__ ls, float* __restrict__ out) {
    extern __shared__ __align__(1024) char smem[];
    const uint32_t sb = smem_u32(smem);
    const int tid = threadIdx.x, wid = tid >> 5, lane = tid & 31;
    const int nb = blockIdx.x, mb = blockIdx.y, b = blockIdx.z;
    const int m0 = mb * M_TILE, n0 = nb * N_TILE;

    // warp layout: 2 (M) x 2 (N), warp tile 64x64
    const int wm = wid & 1, wn = wid >> 1;
    const int warp_m = wm * 64, warp_n = wn * 64;

    float* bias_s = (float*)(smem + SM_BIAS);
    float* ls_s   = (float*)(smem + SM_LS);
    bias_s[tid] = bias[n0 + tid];
    ls_s[tid]   = ls[n0 + tid];

    const __nv_bfloat16* xb = g_xbf + ((size_t)b * L_SZ + m0) * CIN;
    const __nv_bfloat16* wb = g_wmod + ((size_t)b * COUT + n0) * CIN;

    auto load_chunk = [&](int k, int s) {
        const uint32_t sA = sb + SM_STAGE + s * STAGE_BYTES;
        const uint32_t sB = sA + A_BYTES;
        #pragma unroll
        for (int i = 0; i < 8; i++) {  // A: 128 rows x 8 segs = 1024
            int seg = tid + i * NTHREADS; int r = seg >> 3, c = seg & 7;
            cp16(sA + SWZ(r * 128 + c * 16), xb + (size_t)r * CIN + k * K_CHUNK + c * 8);
        }
        #pragma unroll
        for (int i = 0; i < 8; i++) {  // B: 128 rows x 8 segs = 1024
            int seg = tid + i * NTHREADS; int r = seg >> 3, c = seg & 7;
            cp16(sB + SWZ(r * 128 + c * 16), wb + (size_t)r * CIN + k * K_CHUNK + c * 8);
        }
        asm volatile("cp.async.commit_group;" ::: "memory");
    };

    load_chunk(0, 0);
    load_chunk(1, 1);
    load_chunk(2, 2);

    // per-lane ldmatrix address pieces (offsets within a stage)
    const int a_row = warp_m + ((lane >> 3) & 1) * 8 + (lane & 7);
    const uint32_t a_xor = (uint32_t)((a_row & 7) << 4);
    const uint32_t a_rt0 = (uint32_t)(a_row * 128);
    const uint32_t a_kh  = (uint32_t)((lane >> 4) * 16);   // bytes
    const int b_row = warp_n + (lane >> 4) * 8 + (lane & 7);
    const uint32_t b_xor = (uint32_t)((b_row & 7) << 4);
    const uint32_t b_rt0 = (uint32_t)(b_row * 128);
    const uint32_t b_kh  = (uint32_t)(((lane >> 3) & 1) * 16);

    float acc[4][8][4];
    #pragma unroll
    for (int i = 0; i < 4; i++)
        #pragma unroll
        for (int j = 0; j < 8; j++)
            #pragma unroll
            for (int q = 0; q < 4; q++) acc[i][j][q] = 0.f;

    #pragma unroll 1
    for (int k = 0; k < NCHUNK; k++) {
        const int s = k % NSTAGE;
        if (k <= NCHUNK - 3)      cp_wait<2>();
        else if (k == NCHUNK - 2) cp_wait<1>();
        else                      cp_wait<0>();
        __syncthreads();

        const uint32_t sA = sb + SM_STAGE + s * STAGE_BYTES;
        const uint32_t sB = sA + A_BYTES;

        #pragma unroll
        for (int kk = 0; kk < 4; kk++) {
            const uint32_t acol = (uint32_t)(kk * 32) + a_kh;
            const uint32_t bcol = (uint32_t)(kk * 32) + b_kh;
            uint32_t af[4][4];
            #pragma unroll
            for (int mf = 0; mf < 4; mf++)
                ldsm_x4(af[mf], sA + a_rt0 + (uint32_t)(mf * 16 * 128) + (acol ^ a_xor));
            uint32_t bf[4][4];
            #pragma unroll
            for (int nf = 0; nf < 4; nf++)
                ldsm_x4(bf[nf], sB + b_rt0 + (uint32_t)(nf * 16 * 128) + (bcol ^ b_xor));
            #pragma unroll
            for (int mf = 0; mf < 4; mf++)
                #pragma unroll
                for (int nn = 0; nn < 8; nn++)
                    mma16816(acc[mf][nn], af[mf], &bf[nn >> 1][(nn & 1) * 2]);
        }

        __syncthreads();
        if (k + NSTAGE < NCHUNK) load_chunk(k + NSTAGE, s);
    }

    // ---------------- Epilogue ----------------
    const int qr = lane >> 2;          // 0..7
    const int qc = (lane & 3) * 2;     // 0,2,4,6
    #pragma unroll
    for (int mf = 0; mf < 4; mf++) {
        #pragma unroll
        for (int half = 0; half < 2; half++) {
            const int row = warp_m + mf * 16 + qr + half * 8;
            const size_t rowoff = ((size_t)b * L_SZ + m0 + row) * COUT + n0;
            const float* xr = x + rowoff;
            float* outr = out + rowoff;
            #pragma unroll
            for (int nn = 0; nn < 8; nn++) {
                const int c = warp_n + nn * 8 + qc;
                const float d0 = acc[mf][nn][half * 2 + 0];
                const float d1 = acc[mf][nn][half * 2 + 1];
                const float2 xv = *reinterpret_cast<const float2*>(xr + c);
                float2 ov;
                ov.x = epi(d0, bias_s[c],     ls_s[c],     xv.x);
                ov.y = epi(d1, bias_s[c + 1], ls_s[c + 1], xv.y);
                *reinterpret_cast<float2*>(outr + c) = ov;
            }
        }
    }
}

// ============================================================
// Launch
// ============================================================
extern "C" void kernel_launch(void* const* d_in, const int* in_sizes, int n_in,
                              void* d_out, int out_size) {
    (void)in_sizes; (void)n_in; (void)out_size;
    const float* x      = (const float*)d_in[0];
    const float* w      = (const float*)d_in[1];
    const float* weight = (const float*)d_in[2];
    const float* bias   = (const float*)d_in[3];
    const float* aff_w  = (const float*)d_in[4];
    const float* aff_b  = (const float*)d_in[5];
    const float* lsc    = (const float*)d_in[6];
    float* out = (float*)d_out;

    cudaFuncSetAttribute(gemm_kernel, cudaFuncAttributeMaxDynamicSharedMemorySize, SMEM_TOTAL);

    k_convert<<<(B_SZ * L_SZ * CIN / 4) / 256, 256>>>(x);
    k_styles<<<dim3(B_SZ, CIN / 128), 128>>>(w, aff_w, aff_b);
    k_wmod<<<dim3(COUT, B_SZ), 128>>>(weight);
    gemm_kernel<<<dim3(COUT / N_TILE, L_SZ / M_TILE, B_SZ), NTHREADS, SMEM_TOTAL>>>(x, bias, lsc, out);
}